// round 13
// baseline (speedup 1.0000x reference)
#include <cuda_runtime.h>
#include <cstdint>

#define G 128
#define KK 27
#define N_IN 50000
#define N_OUT 100000
#define C_IN 128
#define C_OUT 128
#define GRID_CELLS (G*G*G)

#define TILE_P 128
#define KCH 32
#define CNT_PAD 16
#define AS_STRIDE 36
#define BS_STRIDE 136
#define CS_STRIDE 136
#define GEMM_BLOCKS 296

#define AS_BYTES (TILE_P * AS_STRIDE * 4)
#define BS_BYTES (KCH * BS_STRIDE * 4)
#define SMEM_BYTES (2 * AS_BYTES + 2 * BS_BYTES)

// ---------------- device scratch ----------------
__device__ int      g_grid[GRID_CELLS];
__device__ int      g_pair_cnt[KK * CNT_PAD];
__device__ int2     g_pairs[(size_t)KK * N_OUT];
__device__ uint32_t g_Wtf32[KK * C_IN * C_OUT];

// ---------------- tf32 helpers ----------------
__device__ __forceinline__ uint32_t f2tf32(float f) {
    uint32_t r;
    asm("cvt.rna.tf32.f32 %0, %1;" : "=r"(r) : "f"(f));
    return r;
}
__device__ __forceinline__ void mma_tf32(float c[4], const uint32_t a[4], const uint32_t b[2]) {
    asm volatile(
        "mma.sync.aligned.m16n8k8.row.col.f32.tf32.tf32.f32 "
        "{%0,%1,%2,%3},{%4,%5,%6,%7},{%8,%9},{%0,%1,%2,%3};"
        : "+f"(c[0]), "+f"(c[1]), "+f"(c[2]), "+f"(c[3])
        : "r"(a[0]), "r"(a[1]), "r"(a[2]), "r"(a[3]), "r"(b[0]), "r"(b[1]));
}
__device__ __forceinline__ void cp_async16(uint32_t smem_addr, const void* gptr) {
    asm volatile("cp.async.cg.shared.global [%0], [%1], 16;" :: "r"(smem_addr), "l"(gptr));
}
__device__ __forceinline__ void cp_commit() { asm volatile("cp.async.commit_group;"); }
template<int N> __device__ __forceinline__ void cp_wait() {
    asm volatile("cp.async.wait_group %0;" :: "n"(N));
}
// bulk reduce-add (async proxy; separate group tracker from cp.async)
__device__ __forceinline__ void bulk_red_add_f32(float* gptr, uint32_t smem_addr, int bytes) {
    asm volatile("cp.reduce.async.bulk.global.shared::cta.bulk_group.add.f32 [%0], [%1], %2;"
                 :: "l"(gptr), "r"(smem_addr), "r"(bytes) : "memory");
}
__device__ __forceinline__ void bulk_commit() {
    asm volatile("cp.async.bulk.commit_group;" ::: "memory");
}
__device__ __forceinline__ void bulk_wait_read0() {
    asm volatile("cp.async.bulk.wait_group.read 0;" ::: "memory");
}
__device__ __forceinline__ void bulk_wait0() {
    asm volatile("cp.async.bulk.wait_group 0;" ::: "memory");
}
__device__ __forceinline__ void fence_async_shared() {
    asm volatile("fence.proxy.async.shared::cta;" ::: "memory");
}

// ---------------- kernel 1: zero output + counters + cvt W + scatter grid ----------------
__global__ void k_init(float* __restrict__ out, int out_n,
                       const float* __restrict__ W,
                       const int* __restrict__ inp_pos) {
    int idx = blockIdx.x * blockDim.x + threadIdx.x;
    int stride = gridDim.x * blockDim.x;
    float4* out4 = (float4*)out;
    int n4 = out_n >> 2;
    float4 z = make_float4(0.f, 0.f, 0.f, 0.f);
    for (int i = idx; i < n4; i += stride) out4[i] = z;
    for (int i = idx; i < KK * C_IN * C_OUT; i += stride) g_Wtf32[i] = f2tf32(W[i]);
    if (idx < KK) g_pair_cnt[idx * CNT_PAD] = 0;
    if (idx < N_IN) {
        int x = inp_pos[idx * 3 + 0];
        int y = inp_pos[idx * 3 + 1];
        int zz = inp_pos[idx * 3 + 2];
        atomicMax(&g_grid[(x * G + y) * G + zz], idx + 1);
    }
}

// ---------------- kernel 2: two-pass block-aggregated pair build ----------------
__global__ void __launch_bounds__(256)
k_build_pairs(const int* __restrict__ out_pos) {
    __shared__ int scnt[KK];
    __shared__ int sbase[KK];

    int o = blockIdx.x * blockDim.x + threadIdx.x;
    bool active = (o < N_OUT);
    int x = 0, y = 0, z = 0;
    if (active) {
        x = out_pos[o * 3 + 0];
        y = out_pos[o * 3 + 1];
        z = out_pos[o * 3 + 2];
    }
    if (threadIdx.x < KK) scnt[threadIdx.x] = 0;
    __syncthreads();

    int vcache[KK];
#pragma unroll
    for (int k = 0; k < KK; k++) {
        int v = 0;
        if (active) {
            int nx = x + (k / 9) - 1;
            int ny = y + ((k / 3) % 3) - 1;
            int nz = z + (k % 3) - 1;
            if (((unsigned)nx < G) & ((unsigned)ny < G) & ((unsigned)nz < G))
                v = g_grid[(nx * G + ny) * G + nz];
        }
        vcache[k] = v;
        if (v > 0) atomicAdd(&scnt[k], 1);
    }
    __syncthreads();
    if (threadIdx.x < KK) {
        int c = scnt[threadIdx.x];
        sbase[threadIdx.x] = (c > 0) ? atomicAdd(&g_pair_cnt[threadIdx.x * CNT_PAD], c) : 0;
        scnt[threadIdx.x] = 0;
    }
    __syncthreads();

#pragma unroll
    for (int k = 0; k < KK; k++) {
        int v = vcache[k];
        if (v > 0) {
            int local = atomicAdd(&scnt[k], 1);
            g_pairs[(size_t)k * N_OUT + sbase[k] + local] = make_int2(v - 1, o);
        }
    }
}

// ---------------- kernel 3: pipelined tf32 GEMM, TMA bulk-reduce epilogue ----------------
__global__ void __launch_bounds__(256, 2)
k_gemm(const float* __restrict__ features, float* __restrict__ out) {
    __shared__ __align__(16) char smem_raw[SMEM_BYTES];
    __shared__ int s_out[TILE_P];
    __shared__ int s_tstart[KK + 1];
    __shared__ int s_cnt[KK];

    uint32_t* As0 = reinterpret_cast<uint32_t*>(smem_raw);
    uint32_t* As1 = reinterpret_cast<uint32_t*>(smem_raw + AS_BYTES);
    uint32_t* Bs0 = reinterpret_cast<uint32_t*>(smem_raw + 2 * AS_BYTES);
    uint32_t* Bs1 = reinterpret_cast<uint32_t*>(smem_raw + 2 * AS_BYTES + BS_BYTES);
    float (*Cs)[CS_STRIDE] = reinterpret_cast<float(*)[CS_STRIDE]>(smem_raw);
    const uint32_t cs_smem = (uint32_t)__cvta_generic_to_shared(smem_raw);

    const int tid = threadIdx.x;
    const int lane = tid & 31;
    const int wid = tid >> 5;
    const int warp_m = wid & 1;
    const int warp_n = wid >> 1;
    const int gid = lane >> 2;
    const int tig = lane & 3;

    if (tid < 32) {
        int cnt = 0, c = 0;
        if (tid < KK) {
            cnt = g_pair_cnt[tid * CNT_PAD];
            c = (cnt + TILE_P - 1) / TILE_P;
        }
        int x = c;
#pragma unroll
        for (int d = 1; d < 32; d <<= 1) {
            int y = __shfl_up_sync(0xFFFFFFFFu, x, d);
            if (lane >= d) x += y;
        }
        if (tid < KK) { s_tstart[tid + 1] = x; s_cnt[tid] = cnt; }
        if (tid == 0) s_tstart[0] = 0;
    }
    __syncthreads();
    const int ntiles = s_tstart[KK];

    const int b_row = tid >> 5;
    const int b_c4  = lane;
    const int a_seg = tid & 7;
    const int a_r0  = tid >> 3;

    int t = blockIdx.x;
    if (t >= ntiles) return;

    int kcur = 0;
    while (t >= s_tstart[kcur + 1]) kcur++;
    int tile0 = (t - s_tstart[kcur]) * TILE_P;
    int nvalid = min(TILE_P, s_cnt[kcur] - tile0);
    const int2* pairs_cur = g_pairs + (size_t)kcur * N_OUT;

    int inr[4];
#pragma unroll
    for (int p = 0; p < 4; p++) {
        int row = a_r0 + 32 * p;
        int idx = pairs_cur[tile0 + row].x;
        inr[p] = (row < nvalid) ? idx : -1;
    }
    float4 av[4];
#pragma unroll
    for (int p = 0; p < 4; p++) {
        av[p] = make_float4(0.f, 0.f, 0.f, 0.f);
        if (inr[p] >= 0)
            av[p] = *(const float4*)(features + (size_t)inr[p] * C_IN + a_seg * 4);
    }
    {
        uint32_t bs_base = (uint32_t)__cvta_generic_to_shared(Bs0);
        const uint32_t* Wk0 = g_Wtf32 + (size_t)(KK - 1 - kcur) * C_IN * C_OUT;
#pragma unroll
        for (int p = 0; p < 4; p++) {
            int row = b_row + 8 * p;
            cp_async16(bs_base + (row * BS_STRIDE + b_c4 * 4) * 4,
                       Wk0 + (size_t)row * C_OUT + b_c4 * 4);
        }
        cp_commit();
    }

    while (true) {
        const int k = kcur;
        const uint32_t* __restrict__ Wk = g_Wtf32 + (size_t)(KK - 1 - k) * C_IN * C_OUT;

        bulk_wait_read0();   // prev tile's pass-1 bulk reads of Cs (aliases As) done
        __syncthreads();
        if (tid < TILE_P)
            s_out[tid] = (tid < nvalid) ? pairs_cur[tile0 + tid].y : -1;

        float acc[4][4][4];
#pragma unroll
        for (int mf = 0; mf < 4; mf++)
#pragma unroll
            for (int nf = 0; nf < 4; nf++)
#pragma unroll
                for (int e = 0; e < 4; e++) acc[mf][nf][e] = 0.0f;

#pragma unroll
        for (int kc = 0; kc < 4; kc++) {
            uint32_t* Asb = (kc & 1) ? As1 : As0;
            uint32_t* Bsb = (kc & 1) ? Bs1 : Bs0;

#pragma unroll
            for (int p = 0; p < 4; p++) {
                int row = a_r0 + 32 * p;
                uint4 u = make_uint4(f2tf32(av[p].x), f2tf32(av[p].y),
                                     f2tf32(av[p].z), f2tf32(av[p].w));
                *(uint4*)(Asb + row * AS_STRIDE + a_seg * 4) = u;
            }

            cp_wait<0>();
            __syncthreads();

            if (kc < 3) {
                uint32_t bs_base = (uint32_t)__cvta_generic_to_shared((kc & 1) ? Bs0 : Bs1);
                const uint32_t* src = Wk + (size_t)(kc + 1) * KCH * C_OUT;
#pragma unroll
                for (int p = 0; p < 4; p++) {
                    int row = b_row + 8 * p;
                    cp_async16(bs_base + (row * BS_STRIDE + b_c4 * 4) * 4,
                               src + (size_t)row * C_OUT + b_c4 * 4);
                }
                cp_commit();
                int off = (kc + 1) * KCH + a_seg * 4;
#pragma unroll
                for (int p = 0; p < 4; p++) {
                    av[p] = make_float4(0.f, 0.f, 0.f, 0.f);
                    if (inr[p] >= 0)
                        av[p] = *(const float4*)(features + (size_t)inr[p] * C_IN + off);
                }
            }

#pragma unroll
            for (int ks = 0; ks < 4; ks++) {
                const int k0 = ks * 8;
                uint32_t a[4][4], b[4][2];
#pragma unroll
                for (int mf = 0; mf < 4; mf++) {
                    int r0 = warp_m * 64 + mf * 16 + gid;
                    a[mf][0] = Asb[r0 * AS_STRIDE + k0 + tig];
                    a[mf][1] = Asb[(r0 + 8) * AS_STRIDE + k0 + tig];
                    a[mf][2] = Asb[r0 * AS_STRIDE + k0 + tig + 4];
                    a[mf][3] = Asb[(r0 + 8) * AS_STRIDE + k0 + tig + 4];
                }
#pragma unroll
                for (int nf = 0; nf < 4; nf++) {
                    int n0 = warp_n * 32 + nf * 8 + gid;
                    b[nf][0] = Bsb[(k0 + tig) * BS_STRIDE + n0];
                    b[nf][1] = Bsb[(k0 + tig + 4) * BS_STRIDE + n0];
                }
#pragma unroll
                for (int mf = 0; mf < 4; mf++)
#pragma unroll
                    for (int nf = 0; nf < 4; nf++)
                        mma_tf32(acc[mf][nf], a[mf], b[nf]);
            }
        }
        __syncthreads();   // all MMA reads done before Cs aliases As

        const int tn = t + gridDim.x;
        const bool have_next = (tn < ntiles);
        int tile0n = 0, nvalidn = 0;
        int inrn[4] = {-1, -1, -1, -1};
        if (have_next) {
            while (tn >= s_tstart[kcur + 1]) kcur++;
            tile0n = (tn - s_tstart[kcur]) * TILE_P;
            nvalidn = min(TILE_P, s_cnt[kcur] - tile0n);
            const int2* pn = g_pairs + (size_t)kcur * N_OUT;
#pragma unroll
            for (int p = 0; p < 4; p++) {
                int row = a_r0 + 32 * p;
                int idx = pn[tile0n + row].x;
                inrn[p] = (row < nvalidn) ? idx : -1;
            }
            uint32_t bs_base = (uint32_t)__cvta_generic_to_shared(Bs0);
            const uint32_t* Wn = g_Wtf32 + (size_t)(KK - 1 - kcur) * C_IN * C_OUT;
#pragma unroll
            for (int p = 0; p < 4; p++) {
                int row = b_row + 8 * p;
                cp_async16(bs_base + (row * BS_STRIDE + b_c4 * 4) * 4,
                           Wn + (size_t)row * C_OUT + b_c4 * 4);
            }
            cp_commit();
        }

        // ---- epilogue pass 0: rows 0..63 via bulk reduce-add ----
        if (warp_m == 0) {
#pragma unroll
            for (int mf = 0; mf < 4; mf++)
#pragma unroll
                for (int nf = 0; nf < 4; nf++) {
                    int r = mf * 16 + gid;
                    int col = warp_n * 32 + nf * 8 + tig * 2;
                    *(float2*)&Cs[r][col]     = make_float2(acc[mf][nf][0], acc[mf][nf][1]);
                    *(float2*)&Cs[r + 8][col] = make_float2(acc[mf][nf][2], acc[mf][nf][3]);
                }
        }
        __syncthreads();
        fence_async_shared();
        if (tid < 64) {
            int o = s_out[tid];
            if (o >= 0)
                bulk_red_add_f32(out + (size_t)o * C_OUT,
                                 cs_smem + tid * (CS_STRIDE * 4), C_OUT * 4);
        }
        bulk_commit();

        // next-tile first A gather overlaps the async reduction
        if (have_next) {
#pragma unroll
            for (int p = 0; p < 4; p++) {
                av[p] = make_float4(0.f, 0.f, 0.f, 0.f);
                if (inrn[p] >= 0)
                    av[p] = *(const float4*)(features + (size_t)inrn[p] * C_IN + a_seg * 4);
            }
        }

        // ---- epilogue pass 1: rows 64..127 (reuses Cs region) ----
        bulk_wait_read0();
        __syncthreads();
        if (warp_m == 1) {
#pragma unroll
            for (int mf = 0; mf < 4; mf++)
#pragma unroll
                for (int nf = 0; nf < 4; nf++) {
                    int r = mf * 16 + gid;
                    int col = warp_n * 32 + nf * 8 + tig * 2;
                    *(float2*)&Cs[r][col]     = make_float2(acc[mf][nf][0], acc[mf][nf][1]);
                    *(float2*)&Cs[r + 8][col] = make_float2(acc[mf][nf][2], acc[mf][nf][3]);
                }
        }
        __syncthreads();
        fence_async_shared();
        if (tid < 64) {
            int o = s_out[64 + tid];
            if (o >= 0)
                bulk_red_add_f32(out + (size_t)o * C_OUT,
                                 cs_smem + tid * (CS_STRIDE * 4), C_OUT * 4);
        }
        bulk_commit();

        if (!have_next) break;
        t = tn;
        tile0 = tile0n;
        nvalid = nvalidn;
        pairs_cur = g_pairs + (size_t)kcur * N_OUT;
#pragma unroll
        for (int p = 0; p < 4; p++) inr[p] = inrn[p];
    }

    bulk_wait0();   // drain all bulk reductions before exit
}

// ---------------- launch ----------------
extern "C" void kernel_launch(void* const* d_in, const int* in_sizes, int n_in,
                              void* d_out, int out_size) {
    const float* features = (const float*)d_in[0];
    const float* W        = (const float*)d_in[1];
    const int*   inp_pos  = (const int*)d_in[2];
    const int*   out_pos  = (const int*)d_in[3];
    float* out = (float*)d_out;

    k_init<<<2048, 256>>>(out, out_size, W, inp_pos);
    k_build_pairs<<<(N_OUT + 255) / 256, 256>>>(out_pos);
    k_gemm<<<GEMM_BLOCKS, 256>>>(features, out);
}

// round 14
// speedup vs baseline: 1.0282x; 1.0282x over previous
#include <cuda_runtime.h>
#include <cstdint>

#define G 128
#define KK 27
#define N_IN 50000
#define N_OUT 100000
#define C_IN 128
#define C_OUT 128
#define GRID_CELLS (G*G*G)

#define TILE_P 128
#define KCH 32
#define CNT_PAD 16
#define AS_STRIDE 36
#define BS_STRIDE 136
#define CS_STRIDE 136
#define GEMM_BLOCKS 296

#define AS_BYTES (TILE_P * AS_STRIDE * 4)
#define BS_BYTES (KCH * BS_STRIDE * 4)
#define SMEM_BYTES (2 * AS_BYTES + 2 * BS_BYTES)

// ---------------- device scratch ----------------
__device__ int      g_grid[GRID_CELLS];
__device__ int      g_pair_cnt[KK * CNT_PAD];
__device__ int2     g_pairs[(size_t)KK * N_OUT];
__device__ uint32_t g_Wtf32[KK * C_IN * C_OUT];

// ---------------- tf32 helpers ----------------
__device__ __forceinline__ uint32_t f2tf32(float f) {
    uint32_t r;
    asm("cvt.rna.tf32.f32 %0, %1;" : "=r"(r) : "f"(f));
    return r;
}
__device__ __forceinline__ void mma_tf32(float c[4], const uint32_t a[4], const uint32_t b[2]) {
    asm volatile(
        "mma.sync.aligned.m16n8k8.row.col.f32.tf32.tf32.f32 "
        "{%0,%1,%2,%3},{%4,%5,%6,%7},{%8,%9},{%0,%1,%2,%3};"
        : "+f"(c[0]), "+f"(c[1]), "+f"(c[2]), "+f"(c[3])
        : "r"(a[0]), "r"(a[1]), "r"(a[2]), "r"(a[3]), "r"(b[0]), "r"(b[1]));
}
__device__ __forceinline__ void cp_async16(uint32_t smem_addr, const void* gptr) {
    asm volatile("cp.async.cg.shared.global [%0], [%1], 16;" :: "r"(smem_addr), "l"(gptr));
}
__device__ __forceinline__ void cp_commit() { asm volatile("cp.async.commit_group;"); }
template<int N> __device__ __forceinline__ void cp_wait() {
    asm volatile("cp.async.wait_group %0;" :: "n"(N));
}

// ---------------- kernel 1: zero output + counters + cvt W (vectorized) + scatter grid ----------------
__global__ void k_init(float* __restrict__ out, int out_n,
                       const float* __restrict__ W,
                       const int* __restrict__ inp_pos) {
    int idx = blockIdx.x * blockDim.x + threadIdx.x;
    int stride = gridDim.x * blockDim.x;
    float4* out4 = (float4*)out;
    int n4 = out_n >> 2;
    float4 z = make_float4(0.f, 0.f, 0.f, 0.f);
    for (int i = idx; i < n4; i += stride) out4[i] = z;
    // vectorized W convert: 110592 float4 (< 1 per thread)
    const float4* W4 = (const float4*)W;
    uint4* Wt4 = (uint4*)g_Wtf32;
    int nw4 = (KK * C_IN * C_OUT) >> 2;
    for (int i = idx; i < nw4; i += stride) {
        float4 v = W4[i];
        Wt4[i] = make_uint4(f2tf32(v.x), f2tf32(v.y), f2tf32(v.z), f2tf32(v.w));
    }
    if (idx < KK) g_pair_cnt[idx * CNT_PAD] = 0;
    if (idx < N_IN) {
        int x = inp_pos[idx * 3 + 0];
        int y = inp_pos[idx * 3 + 1];
        int zz = inp_pos[idx * 3 + 2];
        atomicMax(&g_grid[(x * G + y) * G + zz], idx + 1);
    }
}

// ---------------- kernel 2: two-pass block-aggregated pair build ----------------
__global__ void __launch_bounds__(256)
k_build_pairs(const int* __restrict__ out_pos) {
    __shared__ int scnt[KK];
    __shared__ int sbase[KK];

    int o = blockIdx.x * blockDim.x + threadIdx.x;
    bool active = (o < N_OUT);
    int x = 0, y = 0, z = 0;
    if (active) {
        x = out_pos[o * 3 + 0];
        y = out_pos[o * 3 + 1];
        z = out_pos[o * 3 + 2];
    }
    if (threadIdx.x < KK) scnt[threadIdx.x] = 0;
    __syncthreads();

    int vcache[KK];
#pragma unroll
    for (int k = 0; k < KK; k++) {
        int v = 0;
        if (active) {
            int nx = x + (k / 9) - 1;
            int ny = y + ((k / 3) % 3) - 1;
            int nz = z + (k % 3) - 1;
            if (((unsigned)nx < G) & ((unsigned)ny < G) & ((unsigned)nz < G))
                v = g_grid[(nx * G + ny) * G + nz];
        }
        vcache[k] = v;
        if (v > 0) atomicAdd(&scnt[k], 1);
    }
    __syncthreads();
    if (threadIdx.x < KK) {
        int c = scnt[threadIdx.x];
        sbase[threadIdx.x] = (c > 0) ? atomicAdd(&g_pair_cnt[threadIdx.x * CNT_PAD], c) : 0;
        scnt[threadIdx.x] = 0;
    }
    __syncthreads();

#pragma unroll
    for (int k = 0; k < KK; k++) {
        int v = vcache[k];
        if (v > 0) {
            int local = atomicAdd(&scnt[k], 1);
            g_pairs[(size_t)k * N_OUT + sbase[k] + local] = make_int2(v - 1, o);
        }
    }
}

// ---------------- kernel 3: cross-tile pipelined tf32 gather-GEMM-scatter (R12) ----------------
__global__ void __launch_bounds__(256, 2)
k_gemm(const float* __restrict__ features, float* __restrict__ out) {
    __shared__ __align__(16) char smem_raw[SMEM_BYTES];
    __shared__ int s_out[TILE_P];
    __shared__ int s_tstart[KK + 1];
    __shared__ int s_cnt[KK];

    uint32_t* As0 = reinterpret_cast<uint32_t*>(smem_raw);
    uint32_t* As1 = reinterpret_cast<uint32_t*>(smem_raw + AS_BYTES);
    uint32_t* Bs0 = reinterpret_cast<uint32_t*>(smem_raw + 2 * AS_BYTES);
    uint32_t* Bs1 = reinterpret_cast<uint32_t*>(smem_raw + 2 * AS_BYTES + BS_BYTES);
    float (*Cs)[CS_STRIDE] = reinterpret_cast<float(*)[CS_STRIDE]>(smem_raw);

    const int tid = threadIdx.x;
    const int lane = tid & 31;
    const int wid = tid >> 5;
    const int warp_m = wid & 1;
    const int warp_n = wid >> 1;
    const int gid = lane >> 2;
    const int tig = lane & 3;

    if (tid < 32) {
        int cnt = 0, c = 0;
        if (tid < KK) {
            cnt = g_pair_cnt[tid * CNT_PAD];
            c = (cnt + TILE_P - 1) / TILE_P;
        }
        int x = c;
#pragma unroll
        for (int d = 1; d < 32; d <<= 1) {
            int y = __shfl_up_sync(0xFFFFFFFFu, x, d);
            if (lane >= d) x += y;
        }
        if (tid < KK) { s_tstart[tid + 1] = x; s_cnt[tid] = cnt; }
        if (tid == 0) s_tstart[0] = 0;
    }
    __syncthreads();
    const int ntiles = s_tstart[KK];

    const int b_row = tid >> 5;
    const int b_c4  = lane;
    const int a_seg = tid & 7;
    const int a_r0  = tid >> 3;

    int t = blockIdx.x;
    if (t >= ntiles) return;

    int kcur = 0;
    while (t >= s_tstart[kcur + 1]) kcur++;
    int tile0 = (t - s_tstart[kcur]) * TILE_P;
    int nvalid = min(TILE_P, s_cnt[kcur] - tile0);
    const int2* pairs_cur = g_pairs + (size_t)kcur * N_OUT;

    int inr[4];
#pragma unroll
    for (int p = 0; p < 4; p++) {
        int row = a_r0 + 32 * p;
        int idx = pairs_cur[tile0 + row].x;
        inr[p] = (row < nvalid) ? idx : -1;
    }
    float4 av[4];
#pragma unroll
    for (int p = 0; p < 4; p++) {
        av[p] = make_float4(0.f, 0.f, 0.f, 0.f);
        if (inr[p] >= 0)
            av[p] = *(const float4*)(features + (size_t)inr[p] * C_IN + a_seg * 4);
    }
    {
        uint32_t bs_base = (uint32_t)__cvta_generic_to_shared(Bs0);
        const uint32_t* Wk0 = g_Wtf32 + (size_t)(KK - 1 - kcur) * C_IN * C_OUT;
#pragma unroll
        for (int p = 0; p < 4; p++) {
            int row = b_row + 8 * p;
            cp_async16(bs_base + (row * BS_STRIDE + b_c4 * 4) * 4,
                       Wk0 + (size_t)row * C_OUT + b_c4 * 4);
        }
        cp_commit();
    }

    while (true) {
        const int k = kcur;
        const uint32_t* __restrict__ Wk = g_Wtf32 + (size_t)(KK - 1 - k) * C_IN * C_OUT;

        __syncthreads();
        if (tid < TILE_P)
            s_out[tid] = (tid < nvalid) ? pairs_cur[tile0 + tid].y : -1;

        float acc[4][4][4];
#pragma unroll
        for (int mf = 0; mf < 4; mf++)
#pragma unroll
            for (int nf = 0; nf < 4; nf++)
#pragma unroll
                for (int e = 0; e < 4; e++) acc[mf][nf][e] = 0.0f;

#pragma unroll
        for (int kc = 0; kc < 4; kc++) {
            uint32_t* Asb = (kc & 1) ? As1 : As0;
            uint32_t* Bsb = (kc & 1) ? Bs1 : Bs0;

#pragma unroll
            for (int p = 0; p < 4; p++) {
                int row = a_r0 + 32 * p;
                uint4 u = make_uint4(f2tf32(av[p].x), f2tf32(av[p].y),
                                     f2tf32(av[p].z), f2tf32(av[p].w));
                *(uint4*)(Asb + row * AS_STRIDE + a_seg * 4) = u;
            }

            cp_wait<0>();
            __syncthreads();

            if (kc < 3) {
                uint32_t bs_base = (uint32_t)__cvta_generic_to_shared((kc & 1) ? Bs0 : Bs1);
                const uint32_t* src = Wk + (size_t)(kc + 1) * KCH * C_OUT;
#pragma unroll
                for (int p = 0; p < 4; p++) {
                    int row = b_row + 8 * p;
                    cp_async16(bs_base + (row * BS_STRIDE + b_c4 * 4) * 4,
                               src + (size_t)row * C_OUT + b_c4 * 4);
                }
                cp_commit();
                int off = (kc + 1) * KCH + a_seg * 4;
#pragma unroll
                for (int p = 0; p < 4; p++) {
                    av[p] = make_float4(0.f, 0.f, 0.f, 0.f);
                    if (inr[p] >= 0)
                        av[p] = *(const float4*)(features + (size_t)inr[p] * C_IN + off);
                }
            }

#pragma unroll
            for (int ks = 0; ks < 4; ks++) {
                const int k0 = ks * 8;
                uint32_t a[4][4], b[4][2];
#pragma unroll
                for (int mf = 0; mf < 4; mf++) {
                    int r0 = warp_m * 64 + mf * 16 + gid;
                    a[mf][0] = Asb[r0 * AS_STRIDE + k0 + tig];
                    a[mf][1] = Asb[(r0 + 8) * AS_STRIDE + k0 + tig];
                    a[mf][2] = Asb[r0 * AS_STRIDE + k0 + tig + 4];
                    a[mf][3] = Asb[(r0 + 8) * AS_STRIDE + k0 + tig + 4];
                }
#pragma unroll
                for (int nf = 0; nf < 4; nf++) {
                    int n0 = warp_n * 32 + nf * 8 + gid;
                    b[nf][0] = Bsb[(k0 + tig) * BS_STRIDE + n0];
                    b[nf][1] = Bsb[(k0 + tig + 4) * BS_STRIDE + n0];
                }
#pragma unroll
                for (int mf = 0; mf < 4; mf++)
#pragma unroll
                    for (int nf = 0; nf < 4; nf++)
                        mma_tf32(acc[mf][nf], a[mf], b[nf]);
            }
        }
        __syncthreads();

        const int tn = t + gridDim.x;
        const bool have_next = (tn < ntiles);
        int tile0n = 0, nvalidn = 0;
        int inrn[4] = {-1, -1, -1, -1};
        if (have_next) {
            while (tn >= s_tstart[kcur + 1]) kcur++;
            tile0n = (tn - s_tstart[kcur]) * TILE_P;
            nvalidn = min(TILE_P, s_cnt[kcur] - tile0n);
            const int2* pn = g_pairs + (size_t)kcur * N_OUT;
#pragma unroll
            for (int p = 0; p < 4; p++) {
                int row = a_r0 + 32 * p;
                int idx = pn[tile0n + row].x;
                inrn[p] = (row < nvalidn) ? idx : -1;
            }
            uint32_t bs_base = (uint32_t)__cvta_generic_to_shared(Bs0);
            const uint32_t* Wn = g_Wtf32 + (size_t)(KK - 1 - kcur) * C_IN * C_OUT;
#pragma unroll
            for (int p = 0; p < 4; p++) {
                int row = b_row + 8 * p;
                cp_async16(bs_base + (row * BS_STRIDE + b_c4 * 4) * 4,
                           Wn + (size_t)row * C_OUT + b_c4 * 4);
            }
            cp_commit();
        }

        if (warp_m == 0) {
#pragma unroll
            for (int mf = 0; mf < 4; mf++)
#pragma unroll
                for (int nf = 0; nf < 4; nf++) {
                    int r = mf * 16 + gid;
                    int col = warp_n * 32 + nf * 8 + tig * 2;
                    *(float2*)&Cs[r][col]     = make_float2(acc[mf][nf][0], acc[mf][nf][1]);
                    *(float2*)&Cs[r + 8][col] = make_float2(acc[mf][nf][2], acc[mf][nf][3]);
                }
        }
        __syncthreads();
#pragma unroll
        for (int j = 0; j < 8; j++) {
            int id = tid + 256 * j;
            int r = id >> 5;
            int c4 = id & 31;
            int o = s_out[r];
            if (o >= 0) {
                float4 v = *(const float4*)&Cs[r][c4 * 4];
                float* dst = out + (size_t)o * C_OUT + c4 * 4;
                asm volatile("red.global.add.v4.f32 [%0], {%1,%2,%3,%4};"
                             :: "l"(dst), "f"(v.x), "f"(v.y), "f"(v.z), "f"(v.w)
                             : "memory");
            }
        }
        __syncthreads();

        if (have_next) {
#pragma unroll
            for (int p = 0; p < 4; p++) {
                av[p] = make_float4(0.f, 0.f, 0.f, 0.f);
                if (inrn[p] >= 0)
                    av[p] = *(const float4*)(features + (size_t)inrn[p] * C_IN + a_seg * 4);
            }
        }

        if (warp_m == 1) {
#pragma unroll
            for (int mf = 0; mf < 4; mf++)
#pragma unroll
                for (int nf = 0; nf < 4; nf++) {
                    int r = mf * 16 + gid;
                    int col = warp_n * 32 + nf * 8 + tig * 2;
                    *(float2*)&Cs[r][col]     = make_float2(acc[mf][nf][0], acc[mf][nf][1]);
                    *(float2*)&Cs[r + 8][col] = make_float2(acc[mf][nf][2], acc[mf][nf][3]);
                }
        }
        __syncthreads();
#pragma unroll
        for (int j = 0; j < 8; j++) {
            int id = tid + 256 * j;
            int r = id >> 5;
            int c4 = id & 31;
            int o = s_out[64 + r];
            if (o >= 0) {
                float4 v = *(const float4*)&Cs[r][c4 * 4];
                float* dst = out + (size_t)o * C_OUT + c4 * 4;
                asm volatile("red.global.add.v4.f32 [%0], {%1,%2,%3,%4};"
                             :: "l"(dst), "f"(v.x), "f"(v.y), "f"(v.z), "f"(v.w)
                             : "memory");
            }
        }

        if (!have_next) break;
        t = tn;
        tile0 = tile0n;
        nvalid = nvalidn;
        pairs_cur = g_pairs + (size_t)kcur * N_OUT;
#pragma unroll
        for (int p = 0; p < 4; p++) inr[p] = inrn[p];
    }
}

// ---------------- launch ----------------
extern "C" void kernel_launch(void* const* d_in, const int* in_sizes, int n_in,
                              void* d_out, int out_size) {
    const float* features = (const float*)d_in[0];
    const float* W        = (const float*)d_in[1];
    const int*   inp_pos  = (const int*)d_in[2];
    const int*   out_pos  = (const int*)d_in[3];
    float* out = (float*)d_out;

    k_init<<<2048, 256>>>(out, out_size, W, inp_pos);
    k_build_pairs<<<(N_OUT + 255) / 256, 256>>>(out_pos);
    k_gemm<<<GEMM_BLOCKS, 256>>>(features, out);
}

// round 15
// speedup vs baseline: 1.0411x; 1.0125x over previous
#include <cuda_runtime.h>
#include <cstdint>

#define G 128
#define KK 27
#define N_IN 50000
#define N_OUT 100000
#define C_IN 128
#define C_OUT 128
#define GRID_CELLS (G*G*G)

#define TILE_P 128
#define KCH 32
#define CNT_PAD 16
#define AS_STRIDE 36
#define BS_STRIDE 136
#define CS_STRIDE 136
#define GEMM_BLOCKS 296

#define AS_BYTES (TILE_P * AS_STRIDE * 4)
#define BS_BYTES (KCH * BS_STRIDE * 4)
#define SMEM_BYTES (2 * AS_BYTES + 2 * BS_BYTES)

// ---------------- device scratch ----------------
__device__ int      g_grid[GRID_CELLS];
__device__ int      g_pair_cnt[KK * CNT_PAD];
__device__ int2     g_pairs[(size_t)KK * N_OUT];
__device__ uint32_t g_Wtf32[KK * C_IN * C_OUT];

// ---------------- tf32 helpers ----------------
__device__ __forceinline__ uint32_t f2tf32(float f) {
    uint32_t r;
    asm("cvt.rna.tf32.f32 %0, %1;" : "=r"(r) : "f"(f));
    return r;
}
__device__ __forceinline__ void mma_tf32(float c[4], const uint32_t a[4], const uint32_t b[2]) {
    asm volatile(
        "mma.sync.aligned.m16n8k8.row.col.f32.tf32.tf32.f32 "
        "{%0,%1,%2,%3},{%4,%5,%6,%7},{%8,%9},{%0,%1,%2,%3};"
        : "+f"(c[0]), "+f"(c[1]), "+f"(c[2]), "+f"(c[3])
        : "r"(a[0]), "r"(a[1]), "r"(a[2]), "r"(a[3]), "r"(b[0]), "r"(b[1]));
}
__device__ __forceinline__ void cp_async16(uint32_t smem_addr, const void* gptr) {
    asm volatile("cp.async.cg.shared.global [%0], [%1], 16;" :: "r"(smem_addr), "l"(gptr));
}
__device__ __forceinline__ void cp_commit() { asm volatile("cp.async.commit_group;"); }
template<int N> __device__ __forceinline__ void cp_wait() {
    asm volatile("cp.async.wait_group %0;" :: "n"(N));
}

// ---------------- kernel 1: counters + cvt W (vectorized) + scatter grid ----------------
__global__ void k_init(const float* __restrict__ W, const int* __restrict__ inp_pos) {
    int idx = blockIdx.x * blockDim.x + threadIdx.x;
    int stride = gridDim.x * blockDim.x;
    const float4* W4 = (const float4*)W;
    uint4* Wt4 = (uint4*)g_Wtf32;
    int nw4 = (KK * C_IN * C_OUT) >> 2;
    for (int i = idx; i < nw4; i += stride) {
        float4 v = W4[i];
        Wt4[i] = make_uint4(f2tf32(v.x), f2tf32(v.y), f2tf32(v.z), f2tf32(v.w));
    }
    if (idx < KK) g_pair_cnt[idx * CNT_PAD] = 0;
    if (idx < N_IN) {
        int x = inp_pos[idx * 3 + 0];
        int y = inp_pos[idx * 3 + 1];
        int zz = inp_pos[idx * 3 + 2];
        atomicMax(&g_grid[(x * G + y) * G + zz], idx + 1);
    }
}

// ---------------- kernel 2: zero-fill (overlapped) + two-pass pair build ----------------
__global__ void __launch_bounds__(256)
k_build_pairs(const int* __restrict__ out_pos, float* __restrict__ out, int out_n) {
    __shared__ int scnt[KK];
    __shared__ int sbase[KK];

    // fire-and-forget zero-fill: stores overlap the latency-bound grid probes below
    {
        int idx = blockIdx.x * blockDim.x + threadIdx.x;
        int stride = gridDim.x * blockDim.x;
        float4* out4 = (float4*)out;
        int n4 = out_n >> 2;
        float4 z4 = make_float4(0.f, 0.f, 0.f, 0.f);
        for (int i = idx; i < n4; i += stride) out4[i] = z4;
    }

    int o = blockIdx.x * blockDim.x + threadIdx.x;
    bool active = (o < N_OUT);
    int x = 0, y = 0, z = 0;
    if (active) {
        x = out_pos[o * 3 + 0];
        y = out_pos[o * 3 + 1];
        z = out_pos[o * 3 + 2];
    }
    if (threadIdx.x < KK) scnt[threadIdx.x] = 0;
    __syncthreads();

    int vcache[KK];
#pragma unroll
    for (int k = 0; k < KK; k++) {
        int v = 0;
        if (active) {
            int nx = x + (k / 9) - 1;
            int ny = y + ((k / 3) % 3) - 1;
            int nz = z + (k % 3) - 1;
            if (((unsigned)nx < G) & ((unsigned)ny < G) & ((unsigned)nz < G))
                v = g_grid[(nx * G + ny) * G + nz];
        }
        vcache[k] = v;
        if (v > 0) atomicAdd(&scnt[k], 1);
    }
    __syncthreads();
    if (threadIdx.x < KK) {
        int c = scnt[threadIdx.x];
        sbase[threadIdx.x] = (c > 0) ? atomicAdd(&g_pair_cnt[threadIdx.x * CNT_PAD], c) : 0;
        scnt[threadIdx.x] = 0;
    }
    __syncthreads();

#pragma unroll
    for (int k = 0; k < KK; k++) {
        int v = vcache[k];
        if (v > 0) {
            int local = atomicAdd(&scnt[k], 1);
            g_pairs[(size_t)k * N_OUT + sbase[k] + local] = make_int2(v - 1, o);
        }
    }
}

// ---------------- kernel 3: cross-tile pipelined tf32 gather-GEMM-scatter (R12) ----------------
__global__ void __launch_bounds__(256, 2)
k_gemm(const float* __restrict__ features, float* __restrict__ out) {
    __shared__ __align__(16) char smem_raw[SMEM_BYTES];
    __shared__ int s_out[TILE_P];
    __shared__ int s_tstart[KK + 1];
    __shared__ int s_cnt[KK];

    uint32_t* As0 = reinterpret_cast<uint32_t*>(smem_raw);
    uint32_t* As1 = reinterpret_cast<uint32_t*>(smem_raw + AS_BYTES);
    uint32_t* Bs0 = reinterpret_cast<uint32_t*>(smem_raw + 2 * AS_BYTES);
    uint32_t* Bs1 = reinterpret_cast<uint32_t*>(smem_raw + 2 * AS_BYTES + BS_BYTES);
    float (*Cs)[CS_STRIDE] = reinterpret_cast<float(*)[CS_STRIDE]>(smem_raw);

    const int tid = threadIdx.x;
    const int lane = tid & 31;
    const int wid = tid >> 5;
    const int warp_m = wid & 1;
    const int warp_n = wid >> 1;
    const int gid = lane >> 2;
    const int tig = lane & 3;

    if (tid < 32) {
        int cnt = 0, c = 0;
        if (tid < KK) {
            cnt = g_pair_cnt[tid * CNT_PAD];
            c = (cnt + TILE_P - 1) / TILE_P;
        }
        int x = c;
#pragma unroll
        for (int d = 1; d < 32; d <<= 1) {
            int y = __shfl_up_sync(0xFFFFFFFFu, x, d);
            if (lane >= d) x += y;
        }
        if (tid < KK) { s_tstart[tid + 1] = x; s_cnt[tid] = cnt; }
        if (tid == 0) s_tstart[0] = 0;
    }
    __syncthreads();
    const int ntiles = s_tstart[KK];

    const int b_row = tid >> 5;
    const int b_c4  = lane;
    const int a_seg = tid & 7;
    const int a_r0  = tid >> 3;

    int t = blockIdx.x;
    if (t >= ntiles) return;

    int kcur = 0;
    while (t >= s_tstart[kcur + 1]) kcur++;
    int tile0 = (t - s_tstart[kcur]) * TILE_P;
    int nvalid = min(TILE_P, s_cnt[kcur] - tile0);
    const int2* pairs_cur = g_pairs + (size_t)kcur * N_OUT;

    int inr[4];
#pragma unroll
    for (int p = 0; p < 4; p++) {
        int row = a_r0 + 32 * p;
        int idx = pairs_cur[tile0 + row].x;
        inr[p] = (row < nvalid) ? idx : -1;
    }
    float4 av[4];
#pragma unroll
    for (int p = 0; p < 4; p++) {
        av[p] = make_float4(0.f, 0.f, 0.f, 0.f);
        if (inr[p] >= 0)
            av[p] = *(const float4*)(features + (size_t)inr[p] * C_IN + a_seg * 4);
    }
    {
        uint32_t bs_base = (uint32_t)__cvta_generic_to_shared(Bs0);
        const uint32_t* Wk0 = g_Wtf32 + (size_t)(KK - 1 - kcur) * C_IN * C_OUT;
#pragma unroll
        for (int p = 0; p < 4; p++) {
            int row = b_row + 8 * p;
            cp_async16(bs_base + (row * BS_STRIDE + b_c4 * 4) * 4,
                       Wk0 + (size_t)row * C_OUT + b_c4 * 4);
        }
        cp_commit();
    }

    while (true) {
        const int k = kcur;
        const uint32_t* __restrict__ Wk = g_Wtf32 + (size_t)(KK - 1 - k) * C_IN * C_OUT;

        __syncthreads();
        if (tid < TILE_P)
            s_out[tid] = (tid < nvalid) ? pairs_cur[tile0 + tid].y : -1;

        float acc[4][4][4];
#pragma unroll
        for (int mf = 0; mf < 4; mf++)
#pragma unroll
            for (int nf = 0; nf < 4; nf++)
#pragma unroll
                for (int e = 0; e < 4; e++) acc[mf][nf][e] = 0.0f;

#pragma unroll
        for (int kc = 0; kc < 4; kc++) {
            uint32_t* Asb = (kc & 1) ? As1 : As0;
            uint32_t* Bsb = (kc & 1) ? Bs1 : Bs0;

#pragma unroll
            for (int p = 0; p < 4; p++) {
                int row = a_r0 + 32 * p;
                uint4 u = make_uint4(f2tf32(av[p].x), f2tf32(av[p].y),
                                     f2tf32(av[p].z), f2tf32(av[p].w));
                *(uint4*)(Asb + row * AS_STRIDE + a_seg * 4) = u;
            }

            cp_wait<0>();
            __syncthreads();

            if (kc < 3) {
                uint32_t bs_base = (uint32_t)__cvta_generic_to_shared((kc & 1) ? Bs0 : Bs1);
                const uint32_t* src = Wk + (size_t)(kc + 1) * KCH * C_OUT;
#pragma unroll
                for (int p = 0; p < 4; p++) {
                    int row = b_row + 8 * p;
                    cp_async16(bs_base + (row * BS_STRIDE + b_c4 * 4) * 4,
                               src + (size_t)row * C_OUT + b_c4 * 4);
                }
                cp_commit();
                int off = (kc + 1) * KCH + a_seg * 4;
#pragma unroll
                for (int p = 0; p < 4; p++) {
                    av[p] = make_float4(0.f, 0.f, 0.f, 0.f);
                    if (inr[p] >= 0)
                        av[p] = *(const float4*)(features + (size_t)inr[p] * C_IN + off);
                }
            }

#pragma unroll
            for (int ks = 0; ks < 4; ks++) {
                const int k0 = ks * 8;
                uint32_t a[4][4], b[4][2];
#pragma unroll
                for (int mf = 0; mf < 4; mf++) {
                    int r0 = warp_m * 64 + mf * 16 + gid;
                    a[mf][0] = Asb[r0 * AS_STRIDE + k0 + tig];
                    a[mf][1] = Asb[(r0 + 8) * AS_STRIDE + k0 + tig];
                    a[mf][2] = Asb[r0 * AS_STRIDE + k0 + tig + 4];
                    a[mf][3] = Asb[(r0 + 8) * AS_STRIDE + k0 + tig + 4];
                }
#pragma unroll
                for (int nf = 0; nf < 4; nf++) {
                    int n0 = warp_n * 32 + nf * 8 + gid;
                    b[nf][0] = Bsb[(k0 + tig) * BS_STRIDE + n0];
                    b[nf][1] = Bsb[(k0 + tig + 4) * BS_STRIDE + n0];
                }
#pragma unroll
                for (int mf = 0; mf < 4; mf++)
#pragma unroll
                    for (int nf = 0; nf < 4; nf++)
                        mma_tf32(acc[mf][nf], a[mf], b[nf]);
            }
        }
        __syncthreads();

        const int tn = t + gridDim.x;
        const bool have_next = (tn < ntiles);
        int tile0n = 0, nvalidn = 0;
        int inrn[4] = {-1, -1, -1, -1};
        if (have_next) {
            while (tn >= s_tstart[kcur + 1]) kcur++;
            tile0n = (tn - s_tstart[kcur]) * TILE_P;
            nvalidn = min(TILE_P, s_cnt[kcur] - tile0n);
            const int2* pn = g_pairs + (size_t)kcur * N_OUT;
#pragma unroll
            for (int p = 0; p < 4; p++) {
                int row = a_r0 + 32 * p;
                int idx = pn[tile0n + row].x;
                inrn[p] = (row < nvalidn) ? idx : -1;
            }
            uint32_t bs_base = (uint32_t)__cvta_generic_to_shared(Bs0);
            const uint32_t* Wn = g_Wtf32 + (size_t)(KK - 1 - kcur) * C_IN * C_OUT;
#pragma unroll
            for (int p = 0; p < 4; p++) {
                int row = b_row + 8 * p;
                cp_async16(bs_base + (row * BS_STRIDE + b_c4 * 4) * 4,
                           Wn + (size_t)row * C_OUT + b_c4 * 4);
            }
            cp_commit();
        }

        if (warp_m == 0) {
#pragma unroll
            for (int mf = 0; mf < 4; mf++)
#pragma unroll
                for (int nf = 0; nf < 4; nf++) {
                    int r = mf * 16 + gid;
                    int col = warp_n * 32 + nf * 8 + tig * 2;
                    *(float2*)&Cs[r][col]     = make_float2(acc[mf][nf][0], acc[mf][nf][1]);
                    *(float2*)&Cs[r + 8][col] = make_float2(acc[mf][nf][2], acc[mf][nf][3]);
                }
        }
        __syncthreads();
#pragma unroll
        for (int j = 0; j < 8; j++) {
            int id = tid + 256 * j;
            int r = id >> 5;
            int c4 = id & 31;
            int o = s_out[r];
            if (o >= 0) {
                float4 v = *(const float4*)&Cs[r][c4 * 4];
                float* dst = out + (size_t)o * C_OUT + c4 * 4;
                asm volatile("red.global.add.v4.f32 [%0], {%1,%2,%3,%4};"
                             :: "l"(dst), "f"(v.x), "f"(v.y), "f"(v.z), "f"(v.w)
                             : "memory");
            }
        }
        __syncthreads();

        if (have_next) {
#pragma unroll
            for (int p = 0; p < 4; p++) {
                av[p] = make_float4(0.f, 0.f, 0.f, 0.f);
                if (inrn[p] >= 0)
                    av[p] = *(const float4*)(features + (size_t)inrn[p] * C_IN + a_seg * 4);
            }
        }

        if (warp_m == 1) {
#pragma unroll
            for (int mf = 0; mf < 4; mf++)
#pragma unroll
                for (int nf = 0; nf < 4; nf++) {
                    int r = mf * 16 + gid;
                    int col = warp_n * 32 + nf * 8 + tig * 2;
                    *(float2*)&Cs[r][col]     = make_float2(acc[mf][nf][0], acc[mf][nf][1]);
                    *(float2*)&Cs[r + 8][col] = make_float2(acc[mf][nf][2], acc[mf][nf][3]);
                }
        }
        __syncthreads();
#pragma unroll
        for (int j = 0; j < 8; j++) {
            int id = tid + 256 * j;
            int r = id >> 5;
            int c4 = id & 31;
            int o = s_out[64 + r];
            if (o >= 0) {
                float4 v = *(const float4*)&Cs[r][c4 * 4];
                float* dst = out + (size_t)o * C_OUT + c4 * 4;
                asm volatile("red.global.add.v4.f32 [%0], {%1,%2,%3,%4};"
                             :: "l"(dst), "f"(v.x), "f"(v.y), "f"(v.z), "f"(v.w)
                             : "memory");
            }
        }

        if (!have_next) break;
        t = tn;
        tile0 = tile0n;
        nvalid = nvalidn;
        pairs_cur = g_pairs + (size_t)kcur * N_OUT;
#pragma unroll
        for (int p = 0; p < 4; p++) inr[p] = inrn[p];
    }
}

// ---------------- launch ----------------
extern "C" void kernel_launch(void* const* d_in, const int* in_sizes, int n_in,
                              void* d_out, int out_size) {
    const float* features = (const float*)d_in[0];
    const float* W        = (const float*)d_in[1];
    const int*   inp_pos  = (const int*)d_in[2];
    const int*   out_pos  = (const int*)d_in[3];
    float* out = (float*)d_out;

    k_init<<<1024, 256>>>(W, inp_pos);
    k_build_pairs<<<(N_OUT + 255) / 256, 256>>>(out_pos, out, out_size);
    k_gemm<<<GEMM_BLOCKS, 256>>>(features, out);
}

// round 16
// speedup vs baseline: 1.0625x; 1.0206x over previous
#include <cuda_runtime.h>
#include <cstdint>

#define G 128
#define KK 27
#define N_IN 50000
#define N_OUT 100000
#define C_IN 128
#define C_OUT 128
#define GRID_CELLS (G*G*G)

#define TILE_P 128
#define KCH 32
#define CNT_PAD 16
#define AS_STRIDE 36
#define BS_STRIDE 136
#define CS_STRIDE 136
#define GEMM_BLOCKS 296

#define AS_BYTES (TILE_P * AS_STRIDE * 4)
#define BS_BYTES (KCH * BS_STRIDE * 4)
#define SMEM_BYTES (2 * AS_BYTES + 2 * BS_BYTES)

// ---------------- device scratch ----------------
__device__ int      g_grid[GRID_CELLS];
__device__ int      g_pair_cnt[KK * CNT_PAD];
__device__ int2     g_pairs[(size_t)KK * N_OUT];
__device__ uint32_t g_Wtf32[KK * C_IN * C_OUT];

// ---------------- tf32 helpers ----------------
__device__ __forceinline__ uint32_t f2tf32(float f) {
    uint32_t r;
    asm("cvt.rna.tf32.f32 %0, %1;" : "=r"(r) : "f"(f));
    return r;
}
__device__ __forceinline__ void mma_tf32(float c[4], const uint32_t a[4], const uint32_t b[2]) {
    asm volatile(
        "mma.sync.aligned.m16n8k8.row.col.f32.tf32.tf32.f32 "
        "{%0,%1,%2,%3},{%4,%5,%6,%7},{%8,%9},{%0,%1,%2,%3};"
        : "+f"(c[0]), "+f"(c[1]), "+f"(c[2]), "+f"(c[3])
        : "r"(a[0]), "r"(a[1]), "r"(a[2]), "r"(a[3]), "r"(b[0]), "r"(b[1]));
}
__device__ __forceinline__ void cp_async16(uint32_t smem_addr, const void* gptr) {
    asm volatile("cp.async.cg.shared.global [%0], [%1], 16;" :: "r"(smem_addr), "l"(gptr));
}
__device__ __forceinline__ void cp_commit() { asm volatile("cp.async.commit_group;"); }
template<int N> __device__ __forceinline__ void cp_wait() {
    asm volatile("cp.async.wait_group %0;" :: "n"(N));
}

// ---------------- kernel 1: counters + cvt W (vectorized) + scatter grid ----------------
__global__ void k_init(const float* __restrict__ W, const int* __restrict__ inp_pos) {
    int idx = blockIdx.x * blockDim.x + threadIdx.x;
    int stride = gridDim.x * blockDim.x;
    const float4* W4 = (const float4*)W;
    uint4* Wt4 = (uint4*)g_Wtf32;
    int nw4 = (KK * C_IN * C_OUT) >> 2;
    for (int i = idx; i < nw4; i += stride) {
        float4 v = W4[i];
        Wt4[i] = make_uint4(f2tf32(v.x), f2tf32(v.y), f2tf32(v.z), f2tf32(v.w));
    }
    if (idx < KK) g_pair_cnt[idx * CNT_PAD] = 0;
    if (idx < N_IN) {
        int x = inp_pos[idx * 3 + 0];
        int y = inp_pos[idx * 3 + 1];
        int zz = inp_pos[idx * 3 + 2];
        atomicMax(&g_grid[(x * G + y) * G + zz], idx + 1);
    }
}

// ---------------- kernel 2: probes first, fill under their latency, then compact ----------------
__global__ void __launch_bounds__(256)
k_build_pairs(const int* __restrict__ out_pos, float* __restrict__ out, int out_n) {
    __shared__ int scnt[KK];
    __shared__ int sbase[KK];

    int o = blockIdx.x * blockDim.x + threadIdx.x;
    bool active = (o < N_OUT);
    int x = 0, y = 0, z = 0;
    if (active) {
        x = out_pos[o * 3 + 0];
        y = out_pos[o * 3 + 1];
        z = out_pos[o * 3 + 2];
    }
    if (threadIdx.x < KK) scnt[threadIdx.x] = 0;

    // (1) issue all 27 probe LDGs — results not consumed yet (MLP=27 in flight)
    int vcache[KK];
#pragma unroll
    for (int k = 0; k < KK; k++) {
        int v = 0;
        if (active) {
            int nx = x + (k / 9) - 1;
            int ny = y + ((k / 3) % 3) - 1;
            int nz = z + (k % 3) - 1;
            if (((unsigned)nx < G) & ((unsigned)ny < G) & ((unsigned)nz < G))
                v = g_grid[(nx * G + ny) * G + nz];
        }
        vcache[k] = v;
    }

    // (2) zero-fill executes under the outstanding probe loads
    {
        int idx = blockIdx.x * blockDim.x + threadIdx.x;
        int stride = gridDim.x * blockDim.x;
        float4* out4 = (float4*)out;
        int n4 = out_n >> 2;
        float4 z4 = make_float4(0.f, 0.f, 0.f, 0.f);
        for (int i = idx; i < n4; i += stride) out4[i] = z4;
    }
    __syncthreads();   // scnt zeroed before use

    // (3) consume probe results: count, reserve, scatter
#pragma unroll
    for (int k = 0; k < KK; k++)
        if (vcache[k] > 0) atomicAdd(&scnt[k], 1);
    __syncthreads();
    if (threadIdx.x < KK) {
        int c = scnt[threadIdx.x];
        sbase[threadIdx.x] = (c > 0) ? atomicAdd(&g_pair_cnt[threadIdx.x * CNT_PAD], c) : 0;
        scnt[threadIdx.x] = 0;
    }
    __syncthreads();

#pragma unroll
    for (int k = 0; k < KK; k++) {
        int v = vcache[k];
        if (v > 0) {
            int local = atomicAdd(&scnt[k], 1);
            g_pairs[(size_t)k * N_OUT + sbase[k] + local] = make_int2(v - 1, o);
        }
    }
}

// ---------------- kernel 3: cross-tile pipelined tf32 gather-GEMM-scatter (R12) ----------------
__global__ void __launch_bounds__(256, 2)
k_gemm(const float* __restrict__ features, float* __restrict__ out) {
    __shared__ __align__(16) char smem_raw[SMEM_BYTES];
    __shared__ int s_out[TILE_P];
    __shared__ int s_tstart[KK + 1];
    __shared__ int s_cnt[KK];

    uint32_t* As0 = reinterpret_cast<uint32_t*>(smem_raw);
    uint32_t* As1 = reinterpret_cast<uint32_t*>(smem_raw + AS_BYTES);
    uint32_t* Bs0 = reinterpret_cast<uint32_t*>(smem_raw + 2 * AS_BYTES);
    uint32_t* Bs1 = reinterpret_cast<uint32_t*>(smem_raw + 2 * AS_BYTES + BS_BYTES);
    float (*Cs)[CS_STRIDE] = reinterpret_cast<float(*)[CS_STRIDE]>(smem_raw);

    const int tid = threadIdx.x;
    const int lane = tid & 31;
    const int wid = tid >> 5;
    const int warp_m = wid & 1;
    const int warp_n = wid >> 1;
    const int gid = lane >> 2;
    const int tig = lane & 3;

    if (tid < 32) {
        int cnt = 0, c = 0;
        if (tid < KK) {
            cnt = g_pair_cnt[tid * CNT_PAD];
            c = (cnt + TILE_P - 1) / TILE_P;
        }
        int x = c;
#pragma unroll
        for (int d = 1; d < 32; d <<= 1) {
            int y = __shfl_up_sync(0xFFFFFFFFu, x, d);
            if (lane >= d) x += y;
        }
        if (tid < KK) { s_tstart[tid + 1] = x; s_cnt[tid] = cnt; }
        if (tid == 0) s_tstart[0] = 0;
    }
    __syncthreads();
    const int ntiles = s_tstart[KK];

    const int b_row = tid >> 5;
    const int b_c4  = lane;
    const int a_seg = tid & 7;
    const int a_r0  = tid >> 3;

    int t = blockIdx.x;
    if (t >= ntiles) return;

    int kcur = 0;
    while (t >= s_tstart[kcur + 1]) kcur++;
    int tile0 = (t - s_tstart[kcur]) * TILE_P;
    int nvalid = min(TILE_P, s_cnt[kcur] - tile0);
    const int2* pairs_cur = g_pairs + (size_t)kcur * N_OUT;

    int inr[4];
#pragma unroll
    for (int p = 0; p < 4; p++) {
        int row = a_r0 + 32 * p;
        int idx = pairs_cur[tile0 + row].x;
        inr[p] = (row < nvalid) ? idx : -1;
    }
    float4 av[4];
#pragma unroll
    for (int p = 0; p < 4; p++) {
        av[p] = make_float4(0.f, 0.f, 0.f, 0.f);
        if (inr[p] >= 0)
            av[p] = *(const float4*)(features + (size_t)inr[p] * C_IN + a_seg * 4);
    }
    {
        uint32_t bs_base = (uint32_t)__cvta_generic_to_shared(Bs0);
        const uint32_t* Wk0 = g_Wtf32 + (size_t)(KK - 1 - kcur) * C_IN * C_OUT;
#pragma unroll
        for (int p = 0; p < 4; p++) {
            int row = b_row + 8 * p;
            cp_async16(bs_base + (row * BS_STRIDE + b_c4 * 4) * 4,
                       Wk0 + (size_t)row * C_OUT + b_c4 * 4);
        }
        cp_commit();
    }

    while (true) {
        const int k = kcur;
        const uint32_t* __restrict__ Wk = g_Wtf32 + (size_t)(KK - 1 - k) * C_IN * C_OUT;

        __syncthreads();
        if (tid < TILE_P)
            s_out[tid] = (tid < nvalid) ? pairs_cur[tile0 + tid].y : -1;

        float acc[4][4][4];
#pragma unroll
        for (int mf = 0; mf < 4; mf++)
#pragma unroll
            for (int nf = 0; nf < 4; nf++)
#pragma unroll
                for (int e = 0; e < 4; e++) acc[mf][nf][e] = 0.0f;

#pragma unroll
        for (int kc = 0; kc < 4; kc++) {
            uint32_t* Asb = (kc & 1) ? As1 : As0;
            uint32_t* Bsb = (kc & 1) ? Bs1 : Bs0;

#pragma unroll
            for (int p = 0; p < 4; p++) {
                int row = a_r0 + 32 * p;
                uint4 u = make_uint4(f2tf32(av[p].x), f2tf32(av[p].y),
                                     f2tf32(av[p].z), f2tf32(av[p].w));
                *(uint4*)(Asb + row * AS_STRIDE + a_seg * 4) = u;
            }

            cp_wait<0>();
            __syncthreads();

            if (kc < 3) {
                uint32_t bs_base = (uint32_t)__cvta_generic_to_shared((kc & 1) ? Bs0 : Bs1);
                const uint32_t* src = Wk + (size_t)(kc + 1) * KCH * C_OUT;
#pragma unroll
                for (int p = 0; p < 4; p++) {
                    int row = b_row + 8 * p;
                    cp_async16(bs_base + (row * BS_STRIDE + b_c4 * 4) * 4,
                               src + (size_t)row * C_OUT + b_c4 * 4);
                }
                cp_commit();
                int off = (kc + 1) * KCH + a_seg * 4;
#pragma unroll
                for (int p = 0; p < 4; p++) {
                    av[p] = make_float4(0.f, 0.f, 0.f, 0.f);
                    if (inr[p] >= 0)
                        av[p] = *(const float4*)(features + (size_t)inr[p] * C_IN + off);
                }
            }

#pragma unroll
            for (int ks = 0; ks < 4; ks++) {
                const int k0 = ks * 8;
                uint32_t a[4][4], b[4][2];
#pragma unroll
                for (int mf = 0; mf < 4; mf++) {
                    int r0 = warp_m * 64 + mf * 16 + gid;
                    a[mf][0] = Asb[r0 * AS_STRIDE + k0 + tig];
                    a[mf][1] = Asb[(r0 + 8) * AS_STRIDE + k0 + tig];
                    a[mf][2] = Asb[r0 * AS_STRIDE + k0 + tig + 4];
                    a[mf][3] = Asb[(r0 + 8) * AS_STRIDE + k0 + tig + 4];
                }
#pragma unroll
                for (int nf = 0; nf < 4; nf++) {
                    int n0 = warp_n * 32 + nf * 8 + gid;
                    b[nf][0] = Bsb[(k0 + tig) * BS_STRIDE + n0];
                    b[nf][1] = Bsb[(k0 + tig + 4) * BS_STRIDE + n0];
                }
#pragma unroll
                for (int mf = 0; mf < 4; mf++)
#pragma unroll
                    for (int nf = 0; nf < 4; nf++)
                        mma_tf32(acc[mf][nf], a[mf], b[nf]);
            }
        }
        __syncthreads();

        const int tn = t + gridDim.x;
        const bool have_next = (tn < ntiles);
        int tile0n = 0, nvalidn = 0;
        int inrn[4] = {-1, -1, -1, -1};
        if (have_next) {
            while (tn >= s_tstart[kcur + 1]) kcur++;
            tile0n = (tn - s_tstart[kcur]) * TILE_P;
            nvalidn = min(TILE_P, s_cnt[kcur] - tile0n);
            const int2* pn = g_pairs + (size_t)kcur * N_OUT;
#pragma unroll
            for (int p = 0; p < 4; p++) {
                int row = a_r0 + 32 * p;
                int idx = pn[tile0n + row].x;
                inrn[p] = (row < nvalidn) ? idx : -1;
            }
            uint32_t bs_base = (uint32_t)__cvta_generic_to_shared(Bs0);
            const uint32_t* Wn = g_Wtf32 + (size_t)(KK - 1 - kcur) * C_IN * C_OUT;
#pragma unroll
            for (int p = 0; p < 4; p++) {
                int row = b_row + 8 * p;
                cp_async16(bs_base + (row * BS_STRIDE + b_c4 * 4) * 4,
                           Wn + (size_t)row * C_OUT + b_c4 * 4);
            }
            cp_commit();
        }

        if (warp_m == 0) {
#pragma unroll
            for (int mf = 0; mf < 4; mf++)
#pragma unroll
                for (int nf = 0; nf < 4; nf++) {
                    int r = mf * 16 + gid;
                    int col = warp_n * 32 + nf * 8 + tig * 2;
                    *(float2*)&Cs[r][col]     = make_float2(acc[mf][nf][0], acc[mf][nf][1]);
                    *(float2*)&Cs[r + 8][col] = make_float2(acc[mf][nf][2], acc[mf][nf][3]);
                }
        }
        __syncthreads();
#pragma unroll
        for (int j = 0; j < 8; j++) {
            int id = tid + 256 * j;
            int r = id >> 5;
            int c4 = id & 31;
            int o = s_out[r];
            if (o >= 0) {
                float4 v = *(const float4*)&Cs[r][c4 * 4];
                float* dst = out + (size_t)o * C_OUT + c4 * 4;
                asm volatile("red.global.add.v4.f32 [%0], {%1,%2,%3,%4};"
                             :: "l"(dst), "f"(v.x), "f"(v.y), "f"(v.z), "f"(v.w)
                             : "memory");
            }
        }
        __syncthreads();

        if (have_next) {
#pragma unroll
            for (int p = 0; p < 4; p++) {
                av[p] = make_float4(0.f, 0.f, 0.f, 0.f);
                if (inrn[p] >= 0)
                    av[p] = *(const float4*)(features + (size_t)inrn[p] * C_IN + a_seg * 4);
            }
        }

        if (warp_m == 1) {
#pragma unroll
            for (int mf = 0; mf < 4; mf++)
#pragma unroll
                for (int nf = 0; nf < 4; nf++) {
                    int r = mf * 16 + gid;
                    int col = warp_n * 32 + nf * 8 + tig * 2;
                    *(float2*)&Cs[r][col]     = make_float2(acc[mf][nf][0], acc[mf][nf][1]);
                    *(float2*)&Cs[r + 8][col] = make_float2(acc[mf][nf][2], acc[mf][nf][3]);
                }
        }
        __syncthreads();
#pragma unroll
        for (int j = 0; j < 8; j++) {
            int id = tid + 256 * j;
            int r = id >> 5;
            int c4 = id & 31;
            int o = s_out[64 + r];
            if (o >= 0) {
                float4 v = *(const float4*)&Cs[r][c4 * 4];
                float* dst = out + (size_t)o * C_OUT + c4 * 4;
                asm volatile("red.global.add.v4.f32 [%0], {%1,%2,%3,%4};"
                             :: "l"(dst), "f"(v.x), "f"(v.y), "f"(v.z), "f"(v.w)
                             : "memory");
            }
        }

        if (!have_next) break;
        t = tn;
        tile0 = tile0n;
        nvalid = nvalidn;
        pairs_cur = g_pairs + (size_t)kcur * N_OUT;
#pragma unroll
        for (int p = 0; p < 4; p++) inr[p] = inrn[p];
    }
}

// ---------------- launch ----------------
extern "C" void kernel_launch(void* const* d_in, const int* in_sizes, int n_in,
                              void* d_out, int out_size) {
    const float* features = (const float*)d_in[0];
    const float* W        = (const float*)d_in[1];
    const int*   inp_pos  = (const int*)d_in[2];
    const int*   out_pos  = (const int*)d_in[3];
    float* out = (float*)d_out;

    k_init<<<1024, 256>>>(W, inp_pos);
    k_build_pairs<<<(N_OUT + 255) / 256, 256>>>(out_pos, out, out_size);
    k_gemm<<<GEMM_BLOCKS, 256>>>(features, out);
}

// round 17
// speedup vs baseline: 1.1000x; 1.0353x over previous
#include <cuda_runtime.h>
#include <cstdint>

#define G 128
#define KK 27
#define N_IN 50000
#define N_OUT 100000
#define C_IN 128
#define C_OUT 128
#define GRID_CELLS (G*G*G)

#define TILE_P 128
#define KCH 32
#define CNT_PAD 16
#define AS_STRIDE 36
#define BS_STRIDE 136
#define CS_STRIDE 136
#define GEMM_BLOCKS 296

#define AS_BYTES (TILE_P * AS_STRIDE * 4)
#define BS_BYTES (KCH * BS_STRIDE * 4)
#define SMEM_BYTES (2 * AS_BYTES + 2 * BS_BYTES)

// ---------------- device scratch ----------------
__device__ int      g_grid[GRID_CELLS];
__device__ int      g_pair_cnt[KK * CNT_PAD];
__device__ int2     g_pairs[(size_t)KK * N_OUT];
__device__ uint32_t g_Wtf32[KK * C_IN * C_OUT];

// ---------------- tf32 helpers ----------------
__device__ __forceinline__ uint32_t f2tf32(float f) {
    uint32_t r;
    asm("cvt.rna.tf32.f32 %0, %1;" : "=r"(r) : "f"(f));
    return r;
}
__device__ __forceinline__ void mma_tf32(float c[4], const uint32_t a[4], const uint32_t b[2]) {
    asm volatile(
        "mma.sync.aligned.m16n8k8.row.col.f32.tf32.tf32.f32 "
        "{%0,%1,%2,%3},{%4,%5,%6,%7},{%8,%9},{%0,%1,%2,%3};"
        : "+f"(c[0]), "+f"(c[1]), "+f"(c[2]), "+f"(c[3])
        : "r"(a[0]), "r"(a[1]), "r"(a[2]), "r"(a[3]), "r"(b[0]), "r"(b[1]));
}
__device__ __forceinline__ void cp_async16(uint32_t smem_addr, const void* gptr) {
    asm volatile("cp.async.cg.shared.global [%0], [%1], 16;" :: "r"(smem_addr), "l"(gptr));
}
__device__ __forceinline__ void cp_commit() { asm volatile("cp.async.commit_group;"); }
template<int N> __device__ __forceinline__ void cp_wait() {
    asm volatile("cp.async.wait_group %0;" :: "n"(N));
}

// ---------------- kernel 1: counters + grid scatter only ----------------
__global__ void k_init(const int* __restrict__ inp_pos) {
    int idx = blockIdx.x * blockDim.x + threadIdx.x;
    if (idx < KK) g_pair_cnt[idx * CNT_PAD] = 0;
    if (idx < N_IN) {
        int x = inp_pos[idx * 3 + 0];
        int y = inp_pos[idx * 3 + 1];
        int zz = inp_pos[idx * 3 + 2];
        atomicMax(&g_grid[(x * G + y) * G + zz], idx + 1);
    }
}

// ---------------- kernel 2: probes first; W-cvt + zero-fill under their latency; compact ----------------
__global__ void __launch_bounds__(256)
k_build_pairs(const int* __restrict__ out_pos, float* __restrict__ out, int out_n,
              const float* __restrict__ W) {
    __shared__ int scnt[KK];
    __shared__ int sbase[KK];

    int o = blockIdx.x * blockDim.x + threadIdx.x;
    bool active = (o < N_OUT);
    int x = 0, y = 0, z = 0;
    if (active) {
        x = out_pos[o * 3 + 0];
        y = out_pos[o * 3 + 1];
        z = out_pos[o * 3 + 2];
    }
    if (threadIdx.x < KK) scnt[threadIdx.x] = 0;

    // (1) issue all 27 probe LDGs — results not consumed yet (MLP=27 in flight)
    int vcache[KK];
#pragma unroll
    for (int k = 0; k < KK; k++) {
        int v = 0;
        if (active) {
            int nx = x + (k / 9) - 1;
            int ny = y + ((k / 3) % 3) - 1;
            int nz = z + (k % 3) - 1;
            if (((unsigned)nx < G) & ((unsigned)ny < G) & ((unsigned)nz < G))
                v = g_grid[(nx * G + ny) * G + nz];
        }
        vcache[k] = v;
    }

    // (2a) W convert under the outstanding probe loads (~1.1 iter/thread)
    {
        int idx = blockIdx.x * blockDim.x + threadIdx.x;
        int stride = gridDim.x * blockDim.x;
        const float4* W4 = (const float4*)W;
        uint4* Wt4 = (uint4*)g_Wtf32;
        int nw4 = (KK * C_IN * C_OUT) >> 2;
        for (int i = idx; i < nw4; i += stride) {
            float4 v = W4[i];
            Wt4[i] = make_uint4(f2tf32(v.x), f2tf32(v.y), f2tf32(v.z), f2tf32(v.w));
        }
    }

    // (2b) zero-fill also under the probe latency shadow
    {
        int idx = blockIdx.x * blockDim.x + threadIdx.x;
        int stride = gridDim.x * blockDim.x;
        float4* out4 = (float4*)out;
        int n4 = out_n >> 2;
        float4 z4 = make_float4(0.f, 0.f, 0.f, 0.f);
        for (int i = idx; i < n4; i += stride) out4[i] = z4;
    }
    __syncthreads();   // scnt zeroed before use

    // (3) consume probe results: count, reserve, scatter
#pragma unroll
    for (int k = 0; k < KK; k++)
        if (vcache[k] > 0) atomicAdd(&scnt[k], 1);
    __syncthreads();
    if (threadIdx.x < KK) {
        int c = scnt[threadIdx.x];
        sbase[threadIdx.x] = (c > 0) ? atomicAdd(&g_pair_cnt[threadIdx.x * CNT_PAD], c) : 0;
        scnt[threadIdx.x] = 0;
    }
    __syncthreads();

#pragma unroll
    for (int k = 0; k < KK; k++) {
        int v = vcache[k];
        if (v > 0) {
            int local = atomicAdd(&scnt[k], 1);
            g_pairs[(size_t)k * N_OUT + sbase[k] + local] = make_int2(v - 1, o);
        }
    }
}

// ---------------- kernel 3: cross-tile pipelined tf32 gather-GEMM-scatter (R12) ----------------
__global__ void __launch_bounds__(256, 2)
k_gemm(const float* __restrict__ features, float* __restrict__ out) {
    __shared__ __align__(16) char smem_raw[SMEM_BYTES];
    __shared__ int s_out[TILE_P];
    __shared__ int s_tstart[KK + 1];
    __shared__ int s_cnt[KK];

    uint32_t* As0 = reinterpret_cast<uint32_t*>(smem_raw);
    uint32_t* As1 = reinterpret_cast<uint32_t*>(smem_raw + AS_BYTES);
    uint32_t* Bs0 = reinterpret_cast<uint32_t*>(smem_raw + 2 * AS_BYTES);
    uint32_t* Bs1 = reinterpret_cast<uint32_t*>(smem_raw + 2 * AS_BYTES + BS_BYTES);
    float (*Cs)[CS_STRIDE] = reinterpret_cast<float(*)[CS_STRIDE]>(smem_raw);

    const int tid = threadIdx.x;
    const int lane = tid & 31;
    const int wid = tid >> 5;
    const int warp_m = wid & 1;
    const int warp_n = wid >> 1;
    const int gid = lane >> 2;
    const int tig = lane & 3;

    if (tid < 32) {
        int cnt = 0, c = 0;
        if (tid < KK) {
            cnt = g_pair_cnt[tid * CNT_PAD];
            c = (cnt + TILE_P - 1) / TILE_P;
        }
        int x = c;
#pragma unroll
        for (int d = 1; d < 32; d <<= 1) {
            int y = __shfl_up_sync(0xFFFFFFFFu, x, d);
            if (lane >= d) x += y;
        }
        if (tid < KK) { s_tstart[tid + 1] = x; s_cnt[tid] = cnt; }
        if (tid == 0) s_tstart[0] = 0;
    }
    __syncthreads();
    const int ntiles = s_tstart[KK];

    const int b_row = tid >> 5;
    const int b_c4  = lane;
    const int a_seg = tid & 7;
    const int a_r0  = tid >> 3;

    int t = blockIdx.x;
    if (t >= ntiles) return;

    int kcur = 0;
    while (t >= s_tstart[kcur + 1]) kcur++;
    int tile0 = (t - s_tstart[kcur]) * TILE_P;
    int nvalid = min(TILE_P, s_cnt[kcur] - tile0);
    const int2* pairs_cur = g_pairs + (size_t)kcur * N_OUT;

    int inr[4];
#pragma unroll
    for (int p = 0; p < 4; p++) {
        int row = a_r0 + 32 * p;
        int idx = pairs_cur[tile0 + row].x;
        inr[p] = (row < nvalid) ? idx : -1;
    }
    float4 av[4];
#pragma unroll
    for (int p = 0; p < 4; p++) {
        av[p] = make_float4(0.f, 0.f, 0.f, 0.f);
        if (inr[p] >= 0)
            av[p] = *(const float4*)(features + (size_t)inr[p] * C_IN + a_seg * 4);
    }
    {
        uint32_t bs_base = (uint32_t)__cvta_generic_to_shared(Bs0);
        const uint32_t* Wk0 = g_Wtf32 + (size_t)(KK - 1 - kcur) * C_IN * C_OUT;
#pragma unroll
        for (int p = 0; p < 4; p++) {
            int row = b_row + 8 * p;
            cp_async16(bs_base + (row * BS_STRIDE + b_c4 * 4) * 4,
                       Wk0 + (size_t)row * C_OUT + b_c4 * 4);
        }
        cp_commit();
    }

    while (true) {
        const int k = kcur;
        const uint32_t* __restrict__ Wk = g_Wtf32 + (size_t)(KK - 1 - k) * C_IN * C_OUT;

        __syncthreads();
        if (tid < TILE_P)
            s_out[tid] = (tid < nvalid) ? pairs_cur[tile0 + tid].y : -1;

        float acc[4][4][4];
#pragma unroll
        for (int mf = 0; mf < 4; mf++)
#pragma unroll
            for (int nf = 0; nf < 4; nf++)
#pragma unroll
                for (int e = 0; e < 4; e++) acc[mf][nf][e] = 0.0f;

#pragma unroll
        for (int kc = 0; kc < 4; kc++) {
            uint32_t* Asb = (kc & 1) ? As1 : As0;
            uint32_t* Bsb = (kc & 1) ? Bs1 : Bs0;

#pragma unroll
            for (int p = 0; p < 4; p++) {
                int row = a_r0 + 32 * p;
                uint4 u = make_uint4(f2tf32(av[p].x), f2tf32(av[p].y),
                                     f2tf32(av[p].z), f2tf32(av[p].w));
                *(uint4*)(Asb + row * AS_STRIDE + a_seg * 4) = u;
            }

            cp_wait<0>();
            __syncthreads();

            if (kc < 3) {
                uint32_t bs_base = (uint32_t)__cvta_generic_to_shared((kc & 1) ? Bs0 : Bs1);
                const uint32_t* src = Wk + (size_t)(kc + 1) * KCH * C_OUT;
#pragma unroll
                for (int p = 0; p < 4; p++) {
                    int row = b_row + 8 * p;
                    cp_async16(bs_base + (row * BS_STRIDE + b_c4 * 4) * 4,
                               src + (size_t)row * C_OUT + b_c4 * 4);
                }
                cp_commit();
                int off = (kc + 1) * KCH + a_seg * 4;
#pragma unroll
                for (int p = 0; p < 4; p++) {
                    av[p] = make_float4(0.f, 0.f, 0.f, 0.f);
                    if (inr[p] >= 0)
                        av[p] = *(const float4*)(features + (size_t)inr[p] * C_IN + off);
                }
            }

#pragma unroll
            for (int ks = 0; ks < 4; ks++) {
                const int k0 = ks * 8;
                uint32_t a[4][4], b[4][2];
#pragma unroll
                for (int mf = 0; mf < 4; mf++) {
                    int r0 = warp_m * 64 + mf * 16 + gid;
                    a[mf][0] = Asb[r0 * AS_STRIDE + k0 + tig];
                    a[mf][1] = Asb[(r0 + 8) * AS_STRIDE + k0 + tig];
                    a[mf][2] = Asb[r0 * AS_STRIDE + k0 + tig + 4];
                    a[mf][3] = Asb[(r0 + 8) * AS_STRIDE + k0 + tig + 4];
                }
#pragma unroll
                for (int nf = 0; nf < 4; nf++) {
                    int n0 = warp_n * 32 + nf * 8 + gid;
                    b[nf][0] = Bsb[(k0 + tig) * BS_STRIDE + n0];
                    b[nf][1] = Bsb[(k0 + tig + 4) * BS_STRIDE + n0];
                }
#pragma unroll
                for (int mf = 0; mf < 4; mf++)
#pragma unroll
                    for (int nf = 0; nf < 4; nf++)
                        mma_tf32(acc[mf][nf], a[mf], b[nf]);
            }
        }
        __syncthreads();

        const int tn = t + gridDim.x;
        const bool have_next = (tn < ntiles);
        int tile0n = 0, nvalidn = 0;
        int inrn[4] = {-1, -1, -1, -1};
        if (have_next) {
            while (tn >= s_tstart[kcur + 1]) kcur++;
            tile0n = (tn - s_tstart[kcur]) * TILE_P;
            nvalidn = min(TILE_P, s_cnt[kcur] - tile0n);
            const int2* pn = g_pairs + (size_t)kcur * N_OUT;
#pragma unroll
            for (int p = 0; p < 4; p++) {
                int row = a_r0 + 32 * p;
                int idx = pn[tile0n + row].x;
                inrn[p] = (row < nvalidn) ? idx : -1;
            }
            uint32_t bs_base = (uint32_t)__cvta_generic_to_shared(Bs0);
            const uint32_t* Wn = g_Wtf32 + (size_t)(KK - 1 - kcur) * C_IN * C_OUT;
#pragma unroll
            for (int p = 0; p < 4; p++) {
                int row = b_row + 8 * p;
                cp_async16(bs_base + (row * BS_STRIDE + b_c4 * 4) * 4,
                           Wn + (size_t)row * C_OUT + b_c4 * 4);
            }
            cp_commit();
        }

        if (warp_m == 0) {
#pragma unroll
            for (int mf = 0; mf < 4; mf++)
#pragma unroll
                for (int nf = 0; nf < 4; nf++) {
                    int r = mf * 16 + gid;
                    int col = warp_n * 32 + nf * 8 + tig * 2;
                    *(float2*)&Cs[r][col]     = make_float2(acc[mf][nf][0], acc[mf][nf][1]);
                    *(float2*)&Cs[r + 8][col] = make_float2(acc[mf][nf][2], acc[mf][nf][3]);
                }
        }
        __syncthreads();
#pragma unroll
        for (int j = 0; j < 8; j++) {
            int id = tid + 256 * j;
            int r = id >> 5;
            int c4 = id & 31;
            int o = s_out[r];
            if (o >= 0) {
                float4 v = *(const float4*)&Cs[r][c4 * 4];
                float* dst = out + (size_t)o * C_OUT + c4 * 4;
                asm volatile("red.global.add.v4.f32 [%0], {%1,%2,%3,%4};"
                             :: "l"(dst), "f"(v.x), "f"(v.y), "f"(v.z), "f"(v.w)
                             : "memory");
            }
        }
        __syncthreads();

        if (have_next) {
#pragma unroll
            for (int p = 0; p < 4; p++) {
                av[p] = make_float4(0.f, 0.f, 0.f, 0.f);
                if (inrn[p] >= 0)
                    av[p] = *(const float4*)(features + (size_t)inrn[p] * C_IN + a_seg * 4);
            }
        }

        if (warp_m == 1) {
#pragma unroll
            for (int mf = 0; mf < 4; mf++)
#pragma unroll
                for (int nf = 0; nf < 4; nf++) {
                    int r = mf * 16 + gid;
                    int col = warp_n * 32 + nf * 8 + tig * 2;
                    *(float2*)&Cs[r][col]     = make_float2(acc[mf][nf][0], acc[mf][nf][1]);
                    *(float2*)&Cs[r + 8][col] = make_float2(acc[mf][nf][2], acc[mf][nf][3]);
                }
        }
        __syncthreads();
#pragma unroll
        for (int j = 0; j < 8; j++) {
            int id = tid + 256 * j;
            int r = id >> 5;
            int c4 = id & 31;
            int o = s_out[64 + r];
            if (o >= 0) {
                float4 v = *(const float4*)&Cs[r][c4 * 4];
                float* dst = out + (size_t)o * C_OUT + c4 * 4;
                asm volatile("red.global.add.v4.f32 [%0], {%1,%2,%3,%4};"
                             :: "l"(dst), "f"(v.x), "f"(v.y), "f"(v.z), "f"(v.w)
                             : "memory");
            }
        }

        if (!have_next) break;
        t = tn;
        tile0 = tile0n;
        nvalid = nvalidn;
        pairs_cur = g_pairs + (size_t)kcur * N_OUT;
#pragma unroll
        for (int p = 0; p < 4; p++) inr[p] = inrn[p];
    }
}

// ---------------- launch ----------------
extern "C" void kernel_launch(void* const* d_in, const int* in_sizes, int n_in,
                              void* d_out, int out_size) {
    const float* features = (const float*)d_in[0];
    const float* W        = (const float*)d_in[1];
    const int*   inp_pos  = (const int*)d_in[2];
    const int*   out_pos  = (const int*)d_in[3];
    float* out = (float*)d_out;

    k_init<<<(N_IN + 255) / 256, 256>>>(inp_pos);
    k_build_pairs<<<(N_OUT + 255) / 256, 256>>>(out_pos, out, out_size, W);
    k_gemm<<<GEMM_BLOCKS, 256>>>(features, out);
}